// round 2
// baseline (speedup 1.0000x reference)
#include <cuda_runtime.h>
#include <math.h>

#define BB 32
#define TT 4096
#define FF 256
#define KSEL 409            // max(1, int(4096*0.1))
#define NCHUNK 32
#define TCHUNK (TT/NCHUNK)  // 128
#define NSLICE 8
#define SLICE 52            // ceil(409/8)

__device__ float    g_w[BB*TT];
__device__ float    g_part[BB*NCHUNK*FF];
__device__ float    g_corr[BB*NSLICE*FF];
__device__ int      g_idx[BB*KSEL];
__device__ float    g_invZ[BB];

// ---- Kernel A: fused dot + unnormalized weighted sum over a 128-row tile ----
// Phase 1: warp-per-row dots (16 rows/warp), w = exp(tanh(dot+b) - 1) -> smem+gmem.
// Phase 2: thread-per-feature weighted sum; tile re-read hits L1/L2 (just loaded).
__global__ void __launch_bounds__(256) kA(const float* __restrict__ x,
                                          const float* __restrict__ W,
                                          const float* __restrict__ bias) {
    __shared__ float wsh[TCHUNK];
    const int c = blockIdx.x, b = blockIdx.y;
    const int warp = threadIdx.x >> 5, lane = threadIdx.x & 31;
    const float4* wr = (const float4*)W;
    const float4 w0 = __ldg(&wr[lane]);
    const float4 w1 = __ldg(&wr[lane + 32]);
    const float bias0 = bias[0];
    const int t0 = c * TCHUNK;
    const float* xb = x + ((size_t)b * TT + t0) * FF;

    #pragma unroll 4
    for (int r = 0; r < 16; r++) {
        const int row = warp * 16 + r;
        const float4* xr = (const float4*)(xb + (size_t)row * FF);
        float4 a0 = xr[lane];
        float4 a1 = xr[lane + 32];
        float s = a0.x*w0.x + a0.y*w0.y + a0.z*w0.z + a0.w*w0.w
                + a1.x*w1.x + a1.y*w1.y + a1.z*w1.z + a1.w*w1.w;
        #pragma unroll
        for (int o = 16; o; o >>= 1) s += __shfl_xor_sync(0xffffffffu, s, o);
        if (lane == 0) {
            float e = tanhf(s + bias0);
            float w = __expf(e - 1.0f);    // shift-invariant (tanh <= 1)
            wsh[row] = w;
            g_w[b*TT + t0 + row] = w;
        }
    }
    __syncthreads();

    const int f = threadIdx.x;
    const float* xp = xb + f;
    float acc = 0.f;
    #pragma unroll 8
    for (int t = 0; t < TCHUNK; t++) acc += xp[(size_t)t*FF] * wsh[t];
    g_part[(b*NCHUNK + c)*FF + f] = acc;
}

// ---- Kernel B: per-batch Z, exact k-th largest w, deterministic compaction ----
__global__ void __launch_bounds__(512) kB(void) {
    __shared__ float red[512];
    __shared__ unsigned cnt_sh;
    __shared__ unsigned wtot[16];
    const int b = blockIdx.x, tid = threadIdx.x;
    const int lane = tid & 31, wid = tid >> 5;

    float    wv[8];
    unsigned key[8];
    float zsum = 0.f;
    #pragma unroll
    for (int i = 0; i < 8; i++) {
        float w = g_w[b*TT + tid + i*512];
        wv[i] = w;
        key[i] = __float_as_uint(w);       // w > 0 -> raw bits are order-preserving
        zsum += w;
    }
    red[tid] = zsum;
    __syncthreads();
    #pragma unroll
    for (int o = 256; o; o >>= 1) {
        if (tid < o) red[tid] += red[tid + o];
        __syncthreads();
    }
    const float invZ = 1.0f / red[0];

    // radix bisection for the k-th largest key
    unsigned prefix = 0;
    for (int bit = 30; bit >= 0; bit--) {   // w in (0,1]: bit31 always 0
        unsigned test = prefix | (1u << bit);
        if (tid == 0) cnt_sh = 0;
        __syncthreads();
        unsigned cw = 0;
        #pragma unroll
        for (int i = 0; i < 8; i++) cw += (key[i] >= test);
        #pragma unroll
        for (int o = 16; o; o >>= 1) cw += __shfl_xor_sync(0xffffffffu, cw, o);
        if (lane == 0) atomicAdd(&cnt_sh, cw);
        __syncthreads();
        unsigned total = cnt_sh;
        __syncthreads();
        if (total >= KSEL) prefix = test;
    }

    // deterministic stream compaction of indices with key >= prefix
    unsigned cnt = 0;
    #pragma unroll
    for (int i = 0; i < 8; i++) cnt += (key[i] >= prefix);
    unsigned inc = cnt;
    #pragma unroll
    for (int o = 1; o < 32; o <<= 1) {
        unsigned v = __shfl_up_sync(0xffffffffu, inc, o);
        if (lane >= o) inc += v;
    }
    if (lane == 31) wtot[wid] = inc;
    __syncthreads();
    if (tid == 0) {
        unsigned s = 0;
        #pragma unroll
        for (int j = 0; j < 16; j++) { unsigned t = wtot[j]; wtot[j] = s; s += t; }
    }
    __syncthreads();
    unsigned pos = wtot[wid] + inc - cnt;   // exclusive prefix for this thread
    #pragma unroll
    for (int i = 0; i < 8; i++) {
        if (key[i] >= prefix) {
            if (pos < KSEL) g_idx[b*KSEL + pos] = tid + i*512;
            pos++;
        }
    }
    if (tid == 0) g_invZ[b] = invZ;
}

// ---- Kernel C: emphasis correction over top-k rows (10% of x re-read) ----
__global__ void __launch_bounds__(256) kC(const float* __restrict__ x) {
    __shared__ int   idx_sh[SLICE];
    __shared__ float w_sh[SLICE];
    const int s = blockIdx.x, b = blockIdx.y, f = threadIdx.x;
    const int p0 = s * SLICE;
    const int n  = min(KSEL - p0, SLICE);
    if (f < n) {
        int t = g_idx[b*KSEL + p0 + f];
        idx_sh[f] = t;
        w_sh[f]   = g_w[b*TT + t];
    }
    __syncthreads();
    const float* xb = x + (size_t)b * TT * FF + f;
    float acc = 0.f;
    #pragma unroll 4
    for (int p = 0; p < n; p++)
        acc += xb[(size_t)idx_sh[p] * FF] * w_sh[p];
    g_corr[(b*NSLICE + s)*FF + f] = acc;
}

// ---- Kernel D: combine partials, apply 1/Z -> out [B,1,F] ----
__global__ void __launch_bounds__(256) kD(float* __restrict__ out) {
    const int b = blockIdx.x, f = threadIdx.x;
    float s1 = 0.f;
    #pragma unroll
    for (int c = 0; c < NCHUNK; c++) s1 += g_part[(b*NCHUNK + c)*FF + f];
    float sc = 0.f;
    #pragma unroll
    for (int s = 0; s < NSLICE; s++) sc += g_corr[(b*NSLICE + s)*FF + f];
    out[b*FF + f] = (s1 + 0.5f * sc) * g_invZ[b];
}

extern "C" void kernel_launch(void* const* d_in, const int* in_sizes, int n_in,
                              void* d_out, int out_size) {
    const float* x    = (const float*)d_in[0];
    const float* W    = (const float*)d_in[1];
    const float* bias = (const float*)d_in[2];
    float* out = (float*)d_out;

    dim3 gA(NCHUNK, BB);
    kA<<<gA, 256>>>(x, W, bias);
    kB<<<BB, 512>>>();
    dim3 gC(NSLICE, BB);
    kC<<<gC, 256>>>(x);
    kD<<<BB, 256>>>(out);
}